// round 1
// baseline (speedup 1.0000x reference)
#include <cuda_runtime.h>
#include <math.h>

#define NN   20000
#define TT   256
#define EE   320000
#define GG   64
#define CTC  8
#define CPC  16
#define EMB  768
#define FIN  512
#define BN_EPS 1e-5f

// ---------------- scratch (no allocations allowed) ----------------
__device__ float g_h0[(size_t)NN * FIN];     // conv output, N x 512
__device__ float g_agg[(size_t)NN * EMB];    // aggregation buffer (also reused as h2)
__device__ float g_z[(size_t)NN * EMB];      // gin hidden
__device__ float g_h1[(size_t)NN * EMB];     // gin1 output
__device__ float g_pooled[GG * EMB];

// ---------------- zero ----------------
__global__ void zero4_kernel(float4* __restrict__ p, int n4) {
    int i = blockIdx.x * blockDim.x + threadIdx.x;
    if (i < n4) p[i] = make_float4(0.f, 0.f, 0.f, 0.f);
}

// ---------------- temporal conv stack: per-node block ----------------
// conv0 (k=33, 1->8, SAME) -> BN0 -> depthwise conv1 (k=21, SAME) -> relu
// -> pointwise conv2 (8->16) -> BN2 -> relu -> mean-pool over 8 -> h0[n, 32*16]
__global__ __launch_bounds__(256)
void conv_kernel(const float* __restrict__ x,
                 const float* __restrict__ w0,
                 const float* __restrict__ g0, const float* __restrict__ b0,
                 const float* __restrict__ m0, const float* __restrict__ v0,
                 const float* __restrict__ w1,
                 const float* __restrict__ w2,
                 const float* __restrict__ g2, const float* __restrict__ b2,
                 const float* __restrict__ m2, const float* __restrict__ v2,
                 float* __restrict__ h0out)
{
    const int n = blockIdx.x;
    const int t = threadIdx.x;       // 256 = TT

    __shared__ float sx[TT + 32];            // pad 16 each side
    __shared__ float sy[(TT + 20) * 9];      // rows (t+halo10), stride 9, cols 0..7
    __shared__ float sw0[33 * CTC];
    __shared__ float sw1[21 * CTC];
    __shared__ float sw2[CTC * CPC];
    __shared__ float bn0s[CTC], bn0t[CTC], bn2s[CPC], bn2t[CPC];

    sx[16 + t] = x[(size_t)n * TT + t];
    if (t < 16) { sx[t] = 0.f; sx[16 + TT + t] = 0.f; }
    for (int i = t; i < 33 * CTC; i += 256) sw0[i] = w0[i];
    for (int i = t; i < 21 * CTC; i += 256) sw1[i] = w1[i];
    for (int i = t; i < CTC * CPC; i += 256) sw2[i] = w2[i];
    if (t < CTC) { float s = g0[t] * rsqrtf(v0[t] + BN_EPS); bn0s[t] = s; bn0t[t] = b0[t] - m0[t] * s; }
    if (t < CPC) { float s = g2[t] * rsqrtf(v2[t] + BN_EPS); bn2s[t] = s; bn2t[t] = b2[t] - m2[t] * s; }
    __syncthreads();

    // conv0 + BN0
    float y0[CTC];
    #pragma unroll
    for (int c = 0; c < CTC; c++) y0[c] = 0.f;
    #pragma unroll
    for (int k = 0; k < 33; k++) {
        float xv = sx[t + k];
        #pragma unroll
        for (int c = 0; c < CTC; c++) y0[c] = fmaf(xv, sw0[k * CTC + c], y0[c]);
    }
    #pragma unroll
    for (int c = 0; c < CTC; c++) y0[c] = fmaf(y0[c], bn0s[c], bn0t[c]);

    // stage to smem with zero halo of 10 rows on each side
    #pragma unroll
    for (int c = 0; c < CTC; c++) sy[(t + 10) * 9 + c] = y0[c];
    if (t < 10) {
        #pragma unroll
        for (int c = 0; c < CTC; c++) { sy[t * 9 + c] = 0.f; sy[(TT + 10 + t) * 9 + c] = 0.f; }
    }
    __syncthreads();

    // depthwise conv1 + relu
    float yc[CTC];
    #pragma unroll
    for (int c = 0; c < CTC; c++) yc[c] = 0.f;
    #pragma unroll
    for (int k = 0; k < 21; k++) {
        #pragma unroll
        for (int c = 0; c < CTC; c++) yc[c] = fmaf(sy[(t + k) * 9 + c], sw1[k * CTC + c], yc[c]);
    }
    #pragma unroll
    for (int c = 0; c < CTC; c++) yc[c] = fmaxf(yc[c], 0.f);

    // pointwise conv2 + BN2 + relu
    float yp[CPC];
    #pragma unroll
    for (int p = 0; p < CPC; p++) yp[p] = 0.f;
    #pragma unroll
    for (int c = 0; c < CTC; c++) {
        float a = yc[c];
        #pragma unroll
        for (int p = 0; p < CPC; p++) yp[p] = fmaf(a, sw2[c * CPC + p], yp[p]);
    }
    #pragma unroll
    for (int p = 0; p < CPC; p++) yp[p] = fmaxf(fmaf(yp[p], bn2s[p], bn2t[p]), 0.f);

    // mean pool over 8 consecutive t (aligned groups within a warp)
    #pragma unroll
    for (int p = 0; p < CPC; p++) {
        float v = yp[p];
        v += __shfl_xor_sync(0xffffffffu, v, 1);
        v += __shfl_xor_sync(0xffffffffu, v, 2);
        v += __shfl_xor_sync(0xffffffffu, v, 4);
        yp[p] = v * 0.125f;
    }
    if ((t & 7) == 0) {
        int tp = t >> 3;
        float* dst = h0out + (size_t)n * FIN + tp * CPC;
        #pragma unroll
        for (int p = 0; p < CPC; p++) dst[p] = yp[p];
    }
}

// ---------------- edge scatter-add: agg[dst] += h[src] ----------------
__global__ void scatter_kernel(const float* __restrict__ h, const int* __restrict__ ei,
                               float* __restrict__ agg, int F)
{
    const int e = blockIdx.x;
    const int f = threadIdx.x * 4;       // blockDim = F/4
    const int s = ei[e];
    const int d = ei[EE + e];
    const float4 v = *(const float4*)(h + (size_t)s * F + f);
    float* p = agg + (size_t)d * F + f;
    asm volatile("red.global.add.v4.f32 [%0], {%1, %2, %3, %4};"
                 :: "l"(p), "f"(v.x), "f"(v.y), "f"(v.z), "f"(v.w) : "memory");
}

// ---------------- C = relu((A1 [+ A2]) @ B + bias) ----------------
// A: MxK row-major, B: KxN row-major. N % 128 == 0, K % 8 == 0, M guarded.
template <bool FUSE>
__global__ __launch_bounds__(256)
void gemm_bias_relu(const float* __restrict__ A1, const float* __restrict__ A2,
                    const float* __restrict__ B, const float* __restrict__ bias,
                    float* __restrict__ C, int M, int K, int N)
{
    __shared__ float As[8][128];
    __shared__ float Bs[8][128];
    const int tid = threadIdx.x;
    const int row0 = blockIdx.y * 128;
    const int col0 = blockIdx.x * 128;

    const int ar = tid >> 1, ac = (tid & 1) * 4;          // A tile load
    const int brow = tid >> 5, bcol = (tid & 31) * 4;     // B tile load
    const int trow = (tid >> 4) * 8, tcol = (tid & 15) * 8;

    float acc[8][8];
    #pragma unroll
    for (int i = 0; i < 8; i++)
        #pragma unroll
        for (int j = 0; j < 8; j++) acc[i][j] = 0.f;

    for (int k0 = 0; k0 < K; k0 += 8) {
        float4 av = make_float4(0.f, 0.f, 0.f, 0.f);
        const int grow = row0 + ar;
        if (grow < M) {
            av = *(const float4*)(A1 + (size_t)grow * K + k0 + ac);
            if (FUSE) {
                const float4 w = *(const float4*)(A2 + (size_t)grow * K + k0 + ac);
                av.x += w.x; av.y += w.y; av.z += w.z; av.w += w.w;
            }
        }
        As[ac + 0][ar] = av.x; As[ac + 1][ar] = av.y;
        As[ac + 2][ar] = av.z; As[ac + 3][ar] = av.w;
        *(float4*)&Bs[brow][bcol] = *(const float4*)(B + (size_t)(k0 + brow) * N + col0 + bcol);
        __syncthreads();

        #pragma unroll
        for (int kk = 0; kk < 8; kk++) {
            float a[8], b[8];
            #pragma unroll
            for (int i = 0; i < 8; i++) a[i] = As[kk][trow + i];
            #pragma unroll
            for (int j = 0; j < 8; j++) b[j] = Bs[kk][tcol + j];
            #pragma unroll
            for (int i = 0; i < 8; i++)
                #pragma unroll
                for (int j = 0; j < 8; j++) acc[i][j] = fmaf(a[i], b[j], acc[i][j]);
        }
        __syncthreads();
    }

    #pragma unroll
    for (int i = 0; i < 8; i++) {
        const int gr = row0 + trow + i;
        if (gr >= M) continue;
        #pragma unroll
        for (int j = 0; j < 8; j += 4) {
            float4 o;
            o.x = fmaxf(acc[i][j + 0] + bias[col0 + tcol + j + 0], 0.f);
            o.y = fmaxf(acc[i][j + 1] + bias[col0 + tcol + j + 1], 0.f);
            o.z = fmaxf(acc[i][j + 2] + bias[col0 + tcol + j + 2], 0.f);
            o.w = fmaxf(acc[i][j + 3] + bias[col0 + tcol + j + 3], 0.f);
            *(float4*)&C[(size_t)gr * N + col0 + tcol + j] = o;
        }
    }
}

// ---------------- per-graph mean pool (batch is sorted) ----------------
__device__ __forceinline__ int dev_lower_bound(const int* a, int n, int v) {
    int lo = 0, hi = n;
    while (lo < hi) { int m = (lo + hi) >> 1; if (a[m] < v) lo = m + 1; else hi = m; }
    return lo;
}

__global__ void pool_kernel(const float* __restrict__ h, const int* __restrict__ batch,
                            float* __restrict__ pooled)
{
    const int g = blockIdx.x;
    const int t = threadIdx.x;  // 256, EMB = 768 -> 3 cols/thread
    const int lo = dev_lower_bound(batch, NN, g);
    const int hi = dev_lower_bound(batch, NN, g + 1);
    float a0 = 0.f, a1 = 0.f, a2 = 0.f;
    for (int r = lo; r < hi; r++) {
        const float* row = h + (size_t)r * EMB;
        a0 += row[t]; a1 += row[t + 256]; a2 += row[t + 512];
    }
    const float inv = 1.0f / fmaxf((float)(hi - lo), 1.0f);
    pooled[g * EMB + t]       = a0 * inv;
    pooled[g * EMB + t + 256] = a1 * inv;
    pooled[g * EMB + t + 512] = a2 * inv;
}

// ---------------- head: pooled @ dense_w + b -> log_softmax ----------------
__global__ void head_kernel(const float* __restrict__ pooled, const float* __restrict__ dw,
                            const float* __restrict__ db, float* __restrict__ out)
{
    const int g = blockIdx.x;
    const int t = threadIdx.x;  // 128
    float p0 = 0.f, p1 = 0.f, p2 = 0.f, p3 = 0.f;
    for (int k = t; k < EMB; k += 128) {
        const float pv = pooled[g * EMB + k];
        const float4 w = *(const float4*)(dw + k * 4);
        p0 = fmaf(pv, w.x, p0); p1 = fmaf(pv, w.y, p1);
        p2 = fmaf(pv, w.z, p2); p3 = fmaf(pv, w.w, p3);
    }
    __shared__ float s[4][128];
    s[0][t] = p0; s[1][t] = p1; s[2][t] = p2; s[3][t] = p3;
    __syncthreads();
    if (t < 4) {
        float sum = 0.f;
        for (int i = 0; i < 128; i++) sum += s[t][i];
        s[t][0] = sum + db[t];
    }
    __syncthreads();
    if (t == 0) {
        float l0 = s[0][0], l1 = s[1][0], l2 = s[2][0], l3 = s[3][0];
        float m = fmaxf(fmaxf(l0, l1), fmaxf(l2, l3));
        float lse = logf(expf(l0 - m) + expf(l1 - m) + expf(l2 - m) + expf(l3 - m)) + m;
        float* o = out + g * 4;
        o[0] = l0 - lse; o[1] = l1 - lse; o[2] = l2 - lse; o[3] = l3 - lse;
    }
}

// ---------------- launch ----------------
extern "C" void kernel_launch(void* const* d_in, const int* in_sizes, int n_in,
                              void* d_out, int out_size)
{
    const float* x        = (const float*)d_in[0];
    const int*   ei       = (const int*)d_in[1];
    const int*   batch    = (const int*)d_in[2];
    const float* conv0_w  = (const float*)d_in[3];
    const float* bn0_g    = (const float*)d_in[4];
    const float* bn0_b    = (const float*)d_in[5];
    const float* bn0_m    = (const float*)d_in[6];
    const float* bn0_v    = (const float*)d_in[7];
    const float* conv1_w  = (const float*)d_in[8];
    const float* conv2_w  = (const float*)d_in[9];
    const float* bn2_g    = (const float*)d_in[10];
    const float* bn2_b    = (const float*)d_in[11];
    const float* bn2_m    = (const float*)d_in[12];
    const float* bn2_v    = (const float*)d_in[13];
    const float* g1w1     = (const float*)d_in[14];
    const float* g1b1     = (const float*)d_in[15];
    const float* g1w2     = (const float*)d_in[16];
    const float* g1b2     = (const float*)d_in[17];
    const float* g2w1     = (const float*)d_in[18];
    const float* g2b1     = (const float*)d_in[19];
    const float* g2w2     = (const float*)d_in[20];
    const float* g2b2     = (const float*)d_in[21];
    const float* dense_w  = (const float*)d_in[22];
    const float* dense_b  = (const float*)d_in[23];
    float* out = (float*)d_out;

    float *h0, *agg, *z, *h1, *pooled;
    cudaGetSymbolAddress((void**)&h0,     g_h0);
    cudaGetSymbolAddress((void**)&agg,    g_agg);
    cudaGetSymbolAddress((void**)&z,      g_z);
    cudaGetSymbolAddress((void**)&h1,     g_h1);
    cudaGetSymbolAddress((void**)&pooled, g_pooled);

    const dim3 ggrid(EMB / 128, (NN + 127) / 128);

    // zero agg (N x 512 view)
    {
        int n4 = NN * FIN / 4;
        zero4_kernel<<<(n4 + 255) / 256, 256>>>((float4*)agg, n4);
    }
    // temporal conv stack
    conv_kernel<<<NN, 256>>>(x, conv0_w, bn0_g, bn0_b, bn0_m, bn0_v,
                             conv1_w, conv2_w, bn2_g, bn2_b, bn2_m, bn2_v, h0);
    // GIN1
    scatter_kernel<<<EE, FIN / 4>>>(h0, ei, agg, FIN);
    gemm_bias_relu<true ><<<ggrid, 256>>>(h0, agg, g1w1, g1b1, z,  NN, FIN, EMB);
    gemm_bias_relu<false><<<ggrid, 256>>>(z, nullptr, g1w2, g1b2, h1, NN, EMB, EMB);
    // GIN2
    {
        int n4 = NN * EMB / 4;
        zero4_kernel<<<(n4 + 255) / 256, 256>>>((float4*)agg, n4);
    }
    scatter_kernel<<<EE, EMB / 4>>>(h1, ei, agg, EMB);
    gemm_bias_relu<true ><<<ggrid, 256>>>(h1, agg, g2w1, g2b1, z, NN, EMB, EMB);
    gemm_bias_relu<false><<<ggrid, 256>>>(z, nullptr, g2w2, g2b2, agg /* h2 */, NN, EMB, EMB);
    // pool + head
    pool_kernel<<<GG, 256>>>(agg, batch, pooled);
    head_kernel<<<GG, 128>>>(pooled, dense_w, dense_b, out);
}

// round 3
// speedup vs baseline: 1.5617x; 1.5617x over previous
#include <cuda_runtime.h>
#include <math.h>
#include <stdint.h>

#define NN   20000
#define TT   256
#define EE   320000
#define GG   64
#define CTC  8
#define CPC  16
#define EMB  768
#define FIN  512
#define BN_EPS 1e-5f

// ---------------- scratch (no allocations allowed) ----------------
__device__ float g_h0[(size_t)NN * FIN];     // conv output, N x 512
__device__ float g_agg[(size_t)NN * EMB];    // aggregation buffer (also reused as h2)
__device__ float g_z[(size_t)NN * EMB];      // gin hidden
__device__ float g_h1[(size_t)NN * EMB];     // gin1 output
__device__ float g_pooled[GG * EMB];
__device__ float g_wt1[EMB * FIN];           // gin1_w1^T  [768,512] tf32-rounded
__device__ float g_wt2[EMB * EMB];           // gin1_w2^T
__device__ float g_wt3[EMB * EMB];           // gin2_w1^T
__device__ float g_wt4[EMB * EMB];           // gin2_w2^T

// ---------------- helpers ----------------
__device__ __forceinline__ uint32_t smem_u32(const void* p) {
    uint32_t a;
    asm("{ .reg .u64 t; cvta.to.shared.u64 t, %1; cvt.u32.u64 %0, t; }" : "=r"(a) : "l"(p));
    return a;
}
__device__ __forceinline__ float f2tf32(float v) {
    uint32_t o;
    asm("cvt.rna.tf32.f32 %0, %1;" : "=r"(o) : "f"(v));
    return __uint_as_float(o);
}
__device__ __forceinline__ void mma_tf32(float* c, const uint32_t* a, const uint32_t* b) {
    asm volatile("mma.sync.aligned.m16n8k8.row.col.f32.tf32.tf32.f32 "
        "{%0,%1,%2,%3}, {%4,%5,%6,%7}, {%8,%9}, {%0,%1,%2,%3};"
        : "+f"(c[0]), "+f"(c[1]), "+f"(c[2]), "+f"(c[3])
        : "r"(a[0]), "r"(a[1]), "r"(a[2]), "r"(a[3]), "r"(b[0]), "r"(b[1]));
}

// ---------------- zero ----------------
__global__ void zero4_kernel(float4* __restrict__ p, int n4) {
    int i = blockIdx.x * blockDim.x + threadIdx.x;
    if (i < n4) p[i] = make_float4(0.f, 0.f, 0.f, 0.f);
}

// ---------------- weight transpose + tf32 round: Wt[n,k] = rna(W[k,n]) ----------------
__global__ void transpose_tf32_kernel(const float* __restrict__ W, float* __restrict__ Wt,
                                      int K, int Nn)
{
    __shared__ float tile[32][33];
    const int kb = blockIdx.x * 32, nb = blockIdx.y * 32;
    const int tx = threadIdx.x, ty = threadIdx.y;  // 32 x 8
    #pragma unroll
    for (int i = ty; i < 32; i += 8)
        tile[i][tx] = W[(size_t)(kb + i) * Nn + nb + tx];
    __syncthreads();
    #pragma unroll
    for (int i = ty; i < 32; i += 8)
        Wt[(size_t)(nb + i) * K + kb + tx] = f2tf32(tile[tx][i]);
}

// ---------------- temporal conv stack: per-node block ----------------
__global__ __launch_bounds__(256)
void conv_kernel(const float* __restrict__ x,
                 const float* __restrict__ w0,
                 const float* __restrict__ g0, const float* __restrict__ b0,
                 const float* __restrict__ m0, const float* __restrict__ v0,
                 const float* __restrict__ w1,
                 const float* __restrict__ w2,
                 const float* __restrict__ g2, const float* __restrict__ b2,
                 const float* __restrict__ m2, const float* __restrict__ v2,
                 float* __restrict__ h0out)
{
    const int n = blockIdx.x;
    const int t = threadIdx.x;       // 256 = TT

    __shared__ float sx[TT + 32];
    __shared__ float sy[(TT + 20) * 9];
    __shared__ float sw0[33 * CTC];
    __shared__ float sw1[21 * CTC];
    __shared__ float sw2[CTC * CPC];
    __shared__ float bn0s[CTC], bn0t[CTC], bn2s[CPC], bn2t[CPC];

    sx[16 + t] = x[(size_t)n * TT + t];
    if (t < 16) { sx[t] = 0.f; sx[16 + TT + t] = 0.f; }
    for (int i = t; i < 33 * CTC; i += 256) sw0[i] = w0[i];
    for (int i = t; i < 21 * CTC; i += 256) sw1[i] = w1[i];
    for (int i = t; i < CTC * CPC; i += 256) sw2[i] = w2[i];
    if (t < CTC) { float s = g0[t] * rsqrtf(v0[t] + BN_EPS); bn0s[t] = s; bn0t[t] = b0[t] - m0[t] * s; }
    if (t < CPC) { float s = g2[t] * rsqrtf(v2[t] + BN_EPS); bn2s[t] = s; bn2t[t] = b2[t] - m2[t] * s; }
    __syncthreads();

    float y0[CTC];
    #pragma unroll
    for (int c = 0; c < CTC; c++) y0[c] = 0.f;
    #pragma unroll
    for (int k = 0; k < 33; k++) {
        float xv = sx[t + k];
        #pragma unroll
        for (int c = 0; c < CTC; c++) y0[c] = fmaf(xv, sw0[k * CTC + c], y0[c]);
    }
    #pragma unroll
    for (int c = 0; c < CTC; c++) y0[c] = fmaf(y0[c], bn0s[c], bn0t[c]);

    #pragma unroll
    for (int c = 0; c < CTC; c++) sy[(t + 10) * 9 + c] = y0[c];
    if (t < 10) {
        #pragma unroll
        for (int c = 0; c < CTC; c++) { sy[t * 9 + c] = 0.f; sy[(TT + 10 + t) * 9 + c] = 0.f; }
    }
    __syncthreads();

    float yc[CTC];
    #pragma unroll
    for (int c = 0; c < CTC; c++) yc[c] = 0.f;
    #pragma unroll
    for (int k = 0; k < 21; k++) {
        #pragma unroll
        for (int c = 0; c < CTC; c++) yc[c] = fmaf(sy[(t + k) * 9 + c], sw1[k * CTC + c], yc[c]);
    }
    #pragma unroll
    for (int c = 0; c < CTC; c++) yc[c] = fmaxf(yc[c], 0.f);

    float yp[CPC];
    #pragma unroll
    for (int p = 0; p < CPC; p++) yp[p] = 0.f;
    #pragma unroll
    for (int c = 0; c < CTC; c++) {
        float a = yc[c];
        #pragma unroll
        for (int p = 0; p < CPC; p++) yp[p] = fmaf(a, sw2[c * CPC + p], yp[p]);
    }
    #pragma unroll
    for (int p = 0; p < CPC; p++) yp[p] = fmaxf(fmaf(yp[p], bn2s[p], bn2t[p]), 0.f);

    #pragma unroll
    for (int p = 0; p < CPC; p++) {
        float v = yp[p];
        v += __shfl_xor_sync(0xffffffffu, v, 1);
        v += __shfl_xor_sync(0xffffffffu, v, 2);
        v += __shfl_xor_sync(0xffffffffu, v, 4);
        yp[p] = v * 0.125f;
    }
    if ((t & 7) == 0) {
        int tp = t >> 3;
        float* dst = h0out + (size_t)n * FIN + tp * CPC;
        #pragma unroll
        for (int p = 0; p < CPC; p++) dst[p] = yp[p];
    }
}

// ---------------- edge scatter-add: agg[dst] += h[src] ----------------
__global__ void scatter_kernel(const float* __restrict__ h, const int* __restrict__ ei,
                               float* __restrict__ agg, int F)
{
    const int e = blockIdx.x;
    const int f = threadIdx.x * 4;
    const int s = ei[e];
    const int d = ei[EE + e];
    const float4 v = *(const float4*)(h + (size_t)s * F + f);
    float* p = agg + (size_t)d * F + f;
    asm volatile("red.global.add.v4.f32 [%0], {%1, %2, %3, %4};"
                 :: "l"(p), "f"(v.x), "f"(v.y), "f"(v.z), "f"(v.w) : "memory");
}

// ---------------- tf32 mma.sync GEMM: C = relu((A1 [+ A2]) @ Bt^T + bias) ----------------
// A: MxK row-major fp32 (rna->tf32 on the fly). Bt: NxK row-major, pre-rounded tf32.
// 128x128 tile, BK=32, 8 warps (2x4), warp tile 64x32, double-buffered, cp.async for B.
#define BM 128
#define BN 128
#define BK 32
#define LSTR 36
#define TILE_F (BM * LSTR)                  // 4608 floats per tile
#define GEMM_SMEM (4 * TILE_F * 4)          // 2 bufs x (A + B) = 73728 B

template <bool FUSE>
__global__ __launch_bounds__(256, 1)
void gemm_mma(const float* __restrict__ A1, const float* __restrict__ A2,
              const float* __restrict__ Bt, const float* __restrict__ bias,
              float* __restrict__ C, int M, int K, int N)
{
    extern __shared__ float sm[];
    float* Abuf[2] = { sm,              sm + 2 * TILE_F };
    float* Bbuf[2] = { sm + TILE_F,     sm + 3 * TILE_F };

    const int tid  = threadIdx.x;
    const int wid  = tid >> 5;
    const int lane = tid & 31;
    const int g    = lane >> 2;          // 0..7
    const int tq   = lane & 3;           // 0..3
    const int wm   = wid >> 2;           // 0..1
    const int wn   = wid & 3;            // 0..3
    const int row0 = blockIdx.y * BM;
    const int col0 = blockIdx.x * BN;

    // per-thread tile-load coords: 4 iterations, one float4 each
    int lrow[4], lkq[4];
    #pragma unroll
    for (int it = 0; it < 4; it++) {
        const int l = tid + it * 256;
        lrow[it] = l >> 3;
        lkq[it]  = (l & 7) << 2;
    }

    float acc[4][4][4];
    #pragma unroll
    for (int i = 0; i < 4; i++)
        #pragma unroll
        for (int j = 0; j < 4; j++)
            #pragma unroll
            for (int r = 0; r < 4; r++) acc[i][j][r] = 0.f;

    const int nchunk = K / BK;

    auto issue_b = [&](int k0, int buf) {
        #pragma unroll
        for (int it = 0; it < 4; it++) {
            const uint32_t dst = smem_u32(Bbuf[buf] + lrow[it] * LSTR + lkq[it]);
            const float* src = Bt + (size_t)(col0 + lrow[it]) * K + k0 + lkq[it];
            asm volatile("cp.async.ca.shared.global [%0], [%1], 16;" :: "r"(dst), "l"(src));
        }
        asm volatile("cp.async.commit_group;");
    };
    auto load_a = [&](int k0, float4* rA) {
        #pragma unroll
        for (int it = 0; it < 4; it++) {
            float4 v = make_float4(0.f, 0.f, 0.f, 0.f);
            const int gr = row0 + lrow[it];
            if (gr < M) {
                v = *(const float4*)(A1 + (size_t)gr * K + k0 + lkq[it]);
                if (FUSE) {
                    const float4 w = *(const float4*)(A2 + (size_t)gr * K + k0 + lkq[it]);
                    v.x += w.x; v.y += w.y; v.z += w.z; v.w += w.w;
                }
            }
            rA[it] = v;
        }
    };
    auto store_a = [&](const float4* rA, int buf) {
        #pragma unroll
        for (int it = 0; it < 4; it++) {
            float4 v = rA[it];
            v.x = f2tf32(v.x); v.y = f2tf32(v.y); v.z = f2tf32(v.z); v.w = f2tf32(v.w);
            *(float4*)(Abuf[buf] + lrow[it] * LSTR + lkq[it]) = v;
        }
    };

    // prologue: chunk 0 -> buf 0
    {
        float4 rA[4];
        issue_b(0, 0);
        load_a(0, rA);
        store_a(rA, 0);
        asm volatile("cp.async.wait_group 0;");
        __syncthreads();
    }

    for (int c = 0; c < nchunk; c++) {
        const int buf = c & 1;
        const bool more = (c + 1 < nchunk);
        float4 rA[4];
        if (more) {
            issue_b((c + 1) * BK, buf ^ 1);
            load_a((c + 1) * BK, rA);
        }
        // compute on buf
        const float* As = Abuf[buf];
        const float* Bs = Bbuf[buf];
        #pragma unroll
        for (int kk = 0; kk < 4; kk++) {
            const int ka = kk * 8 + tq;
            uint32_t a[4][4], b[4][2];
            #pragma unroll
            for (int fm = 0; fm < 4; fm++) {
                const int r = wm * 64 + fm * 16 + g;
                a[fm][0] = __float_as_uint(As[r * LSTR + ka]);
                a[fm][1] = __float_as_uint(As[(r + 8) * LSTR + ka]);
                a[fm][2] = __float_as_uint(As[r * LSTR + ka + 4]);
                a[fm][3] = __float_as_uint(As[(r + 8) * LSTR + ka + 4]);
            }
            #pragma unroll
            for (int fn = 0; fn < 4; fn++) {
                const int nn = wn * 32 + fn * 8 + g;
                b[fn][0] = __float_as_uint(Bs[nn * LSTR + ka]);
                b[fn][1] = __float_as_uint(Bs[nn * LSTR + ka + 4]);
            }
            #pragma unroll
            for (int fm = 0; fm < 4; fm++)
                #pragma unroll
                for (int fn = 0; fn < 4; fn++)
                    mma_tf32(acc[fm][fn], a[fm], b[fn]);
        }
        __syncthreads();
        if (more) {
            store_a(rA, buf ^ 1);
            asm volatile("cp.async.wait_group 0;");
        }
        __syncthreads();
    }

    // epilogue: bias + relu, float2 stores
    const int t2 = tq * 2;
    #pragma unroll
    for (int fm = 0; fm < 4; fm++) {
        const int r0 = row0 + wm * 64 + fm * 16 + g;
        #pragma unroll
        for (int fn = 0; fn < 4; fn++) {
            const int cc = col0 + wn * 32 + fn * 8 + t2;
            const float2 bv = *(const float2*)(bias + cc);
            if (r0 < M) {
                float2 o;
                o.x = fmaxf(acc[fm][fn][0] + bv.x, 0.f);
                o.y = fmaxf(acc[fm][fn][1] + bv.y, 0.f);
                *(float2*)(C + (size_t)r0 * N + cc) = o;
            }
            if (r0 + 8 < M) {
                float2 o;
                o.x = fmaxf(acc[fm][fn][2] + bv.x, 0.f);
                o.y = fmaxf(acc[fm][fn][3] + bv.y, 0.f);
                *(float2*)(C + (size_t)(r0 + 8) * N + cc) = o;
            }
        }
    }
}

// ---------------- per-graph mean pool (batch is sorted) ----------------
__device__ __forceinline__ int dev_lower_bound(const int* a, int n, int v) {
    int lo = 0, hi = n;
    while (lo < hi) { int m = (lo + hi) >> 1; if (a[m] < v) lo = m + 1; else hi = m; }
    return lo;
}

__global__ void pool_kernel(const float* __restrict__ h, const int* __restrict__ batch,
                            float* __restrict__ pooled)
{
    const int g = blockIdx.x;
    const int t = threadIdx.x;  // 256
    const int lo = dev_lower_bound(batch, NN, g);
    const int hi = dev_lower_bound(batch, NN, g + 1);
    float a0 = 0.f, a1 = 0.f, a2 = 0.f;
    for (int r = lo; r < hi; r++) {
        const float* row = h + (size_t)r * EMB;
        a0 += row[t]; a1 += row[t + 256]; a2 += row[t + 512];
    }
    const float inv = 1.0f / fmaxf((float)(hi - lo), 1.0f);
    pooled[g * EMB + t]       = a0 * inv;
    pooled[g * EMB + t + 256] = a1 * inv;
    pooled[g * EMB + t + 512] = a2 * inv;
}

// ---------------- head ----------------
__global__ void head_kernel(const float* __restrict__ pooled, const float* __restrict__ dw,
                            const float* __restrict__ db, float* __restrict__ out)
{
    const int g = blockIdx.x;
    const int t = threadIdx.x;  // 128
    float p0 = 0.f, p1 = 0.f, p2 = 0.f, p3 = 0.f;
    for (int k = t; k < EMB; k += 128) {
        const float pv = pooled[g * EMB + k];
        const float4 w = *(const float4*)(dw + k * 4);
        p0 = fmaf(pv, w.x, p0); p1 = fmaf(pv, w.y, p1);
        p2 = fmaf(pv, w.z, p2); p3 = fmaf(pv, w.w, p3);
    }
    __shared__ float s[4][128];
    s[0][t] = p0; s[1][t] = p1; s[2][t] = p2; s[3][t] = p3;
    __syncthreads();
    if (t < 4) {
        float sum = 0.f;
        for (int i = 0; i < 128; i++) sum += s[t][i];
        s[t][0] = sum + db[t];
    }
    __syncthreads();
    if (t == 0) {
        float l0 = s[0][0], l1 = s[1][0], l2 = s[2][0], l3 = s[3][0];
        float m = fmaxf(fmaxf(l0, l1), fmaxf(l2, l3));
        float lse = logf(expf(l0 - m) + expf(l1 - m) + expf(l2 - m) + expf(l3 - m)) + m;
        float* o = out + g * 4;
        o[0] = l0 - lse; o[1] = l1 - lse; o[2] = l2 - lse; o[3] = l3 - lse;
    }
}

// ---------------- launch ----------------
extern "C" void kernel_launch(void* const* d_in, const int* in_sizes, int n_in,
                              void* d_out, int out_size)
{
    const float* x        = (const float*)d_in[0];
    const int*   ei       = (const int*)d_in[1];
    const int*   batch    = (const int*)d_in[2];
    const float* conv0_w  = (const float*)d_in[3];
    const float* bn0_g    = (const float*)d_in[4];
    const float* bn0_b    = (const float*)d_in[5];
    const float* bn0_m    = (const float*)d_in[6];
    const float* bn0_v    = (const float*)d_in[7];
    const float* conv1_w  = (const float*)d_in[8];
    const float* conv2_w  = (const float*)d_in[9];
    const float* bn2_g    = (const float*)d_in[10];
    const float* bn2_b    = (const float*)d_in[11];
    const float* bn2_m    = (const float*)d_in[12];
    const float* bn2_v    = (const float*)d_in[13];
    const float* g1w1     = (const float*)d_in[14];
    const float* g1b1     = (const float*)d_in[15];
    const float* g1w2     = (const float*)d_in[16];
    const float* g1b2     = (const float*)d_in[17];
    const float* g2w1     = (const float*)d_in[18];
    const float* g2b1     = (const float*)d_in[19];
    const float* g2w2     = (const float*)d_in[20];
    const float* g2b2     = (const float*)d_in[21];
    const float* dense_w  = (const float*)d_in[22];
    const float* dense_b  = (const float*)d_in[23];
    float* out = (float*)d_out;

    float *h0, *agg, *z, *h1, *pooled, *wt1, *wt2, *wt3, *wt4;
    cudaGetSymbolAddress((void**)&h0,     g_h0);
    cudaGetSymbolAddress((void**)&agg,    g_agg);
    cudaGetSymbolAddress((void**)&z,      g_z);
    cudaGetSymbolAddress((void**)&h1,     g_h1);
    cudaGetSymbolAddress((void**)&pooled, g_pooled);
    cudaGetSymbolAddress((void**)&wt1,    g_wt1);
    cudaGetSymbolAddress((void**)&wt2,    g_wt2);
    cudaGetSymbolAddress((void**)&wt3,    g_wt3);
    cudaGetSymbolAddress((void**)&wt4,    g_wt4);

    cudaFuncSetAttribute(gemm_mma<true>,  cudaFuncAttributeMaxDynamicSharedMemorySize, GEMM_SMEM);
    cudaFuncSetAttribute(gemm_mma<false>, cudaFuncAttributeMaxDynamicSharedMemorySize, GEMM_SMEM);

    const dim3 ggrid(EMB / 128, (NN + 127) / 128);
    const dim3 tb(32, 8);

    // weight transposes (tf32-rounded), independent of data path
    transpose_tf32_kernel<<<dim3(FIN / 32, EMB / 32), tb>>>(g1w1, wt1, FIN, EMB);
    transpose_tf32_kernel<<<dim3(EMB / 32, EMB / 32), tb>>>(g1w2, wt2, EMB, EMB);
    transpose_tf32_kernel<<<dim3(EMB / 32, EMB / 32), tb>>>(g2w1, wt3, EMB, EMB);
    transpose_tf32_kernel<<<dim3(EMB / 32, EMB / 32), tb>>>(g2w2, wt4, EMB, EMB);

    // zero agg (N x 512 view)
    {
        int n4 = NN * FIN / 4;
        zero4_kernel<<<(n4 + 255) / 256, 256>>>((float4*)agg, n4);
    }
    // temporal conv stack
    conv_kernel<<<NN, 256>>>(x, conv0_w, bn0_g, bn0_b, bn0_m, bn0_v,
                             conv1_w, conv2_w, bn2_g, bn2_b, bn2_m, bn2_v, h0);
    // GIN1
    scatter_kernel<<<EE, FIN / 4>>>(h0, ei, agg, FIN);
    gemm_mma<true ><<<ggrid, 256, GEMM_SMEM>>>(h0, agg, wt1, g1b1, z,  NN, FIN, EMB);
    gemm_mma<false><<<ggrid, 256, GEMM_SMEM>>>(z, nullptr, wt2, g1b2, h1, NN, EMB, EMB);
    // GIN2
    {
        int n4 = NN * EMB / 4;
        zero4_kernel<<<(n4 + 255) / 256, 256>>>((float4*)agg, n4);
    }
    scatter_kernel<<<EE, EMB / 4>>>(h1, ei, agg, EMB);
    gemm_mma<true ><<<ggrid, 256, GEMM_SMEM>>>(h1, agg, wt3, g2b1, z, NN, EMB, EMB);
    gemm_mma<false><<<ggrid, 256, GEMM_SMEM>>>(z, nullptr, wt4, g2b2, agg /* h2 */, NN, EMB, EMB);
    // pool + head
    pool_kernel<<<GG, 256>>>(agg, batch, pooled);
    head_kernel<<<GG, 128>>>(pooled, dense_w, dense_b, out);
}

// round 4
// speedup vs baseline: 2.0852x; 1.3353x over previous
#include <cuda_runtime.h>
#include <math.h>
#include <stdint.h>

#define NN   20000
#define TT   256
#define EE   320000
#define GG   64
#define CTC  8
#define CPC  16
#define EMB  768
#define FIN  512
#define BN_EPS 1e-5f

// ---------------- scratch (no allocations allowed) ----------------
__device__ float g_h0[(size_t)NN * FIN];     // conv output, N x 512
__device__ float g_agg[(size_t)NN * EMB];    // X = h + sum(neigh) buffer (512 then 768 view)
__device__ float g_z[(size_t)NN * EMB];      // gin hidden
__device__ float g_h1[(size_t)NN * EMB];     // gin1 output, then h2
__device__ float g_pooled[GG * EMB];
__device__ float g_wt1[EMB * FIN];           // gin1_w1^T  [768,512] tf32-rounded
__device__ float g_wt2[EMB * EMB];           // gin1_w2^T
__device__ float g_wt3[EMB * EMB];           // gin2_w1^T
__device__ float g_wt4[EMB * EMB];           // gin2_w2^T

// ---------------- helpers ----------------
__device__ __forceinline__ uint32_t smem_u32(const void* p) {
    uint32_t a;
    asm("{ .reg .u64 t; cvta.to.shared.u64 t, %1; cvt.u32.u64 %0, t; }" : "=r"(a) : "l"(p));
    return a;
}
__device__ __forceinline__ float f2tf32(float v) {
    uint32_t o;
    asm("cvt.rna.tf32.f32 %0, %1;" : "=r"(o) : "f"(v));
    return __uint_as_float(o);
}
__device__ __forceinline__ void mma_tf32(float* c, const uint32_t* a, const uint32_t* b) {
    asm volatile("mma.sync.aligned.m16n8k8.row.col.f32.tf32.tf32.f32 "
        "{%0,%1,%2,%3}, {%4,%5,%6,%7}, {%8,%9}, {%0,%1,%2,%3};"
        : "+f"(c[0]), "+f"(c[1]), "+f"(c[2]), "+f"(c[3])
        : "r"(a[0]), "r"(a[1]), "r"(a[2]), "r"(a[3]), "r"(b[0]), "r"(b[1]));
}

// ---------------- weight transposes, all four in one launch ----------------
__global__ void transpose_all_kernel(const float* __restrict__ w1, const float* __restrict__ w2,
                                     const float* __restrict__ w3, const float* __restrict__ w4,
                                     float* __restrict__ t1, float* __restrict__ t2,
                                     float* __restrict__ t3, float* __restrict__ t4)
{
    const int which = blockIdx.z;
    const float* W; float* Wt; int K;
    if (which == 0)      { W = w1; Wt = t1; K = FIN; }
    else if (which == 1) { W = w2; Wt = t2; K = EMB; }
    else if (which == 2) { W = w3; Wt = t3; K = EMB; }
    else                 { W = w4; Wt = t4; K = EMB; }
    const int kb = blockIdx.x * 32, nb = blockIdx.y * 32;
    if (kb >= K) return;
    __shared__ float tile[32][33];
    const int tx = threadIdx.x, ty = threadIdx.y;  // 32 x 8
    #pragma unroll
    for (int i = ty; i < 32; i += 8)
        tile[i][tx] = W[(size_t)(kb + i) * EMB + nb + tx];
    __syncthreads();
    #pragma unroll
    for (int i = ty; i < 32; i += 8)
        Wt[(size_t)(nb + i) * K + kb + tx] = f2tf32(tile[tx][i]);
}

// ---------------- temporal conv stack: per-node block ----------------
// writes rounded h0 to BOTH h0out and aggout (agg starts as h, scatter adds on top)
__global__ __launch_bounds__(256)
void conv_kernel(const float* __restrict__ x,
                 const float* __restrict__ w0,
                 const float* __restrict__ g0, const float* __restrict__ b0,
                 const float* __restrict__ m0, const float* __restrict__ v0,
                 const float* __restrict__ w1,
                 const float* __restrict__ w2,
                 const float* __restrict__ g2, const float* __restrict__ b2,
                 const float* __restrict__ m2, const float* __restrict__ v2,
                 float* __restrict__ h0out, float* __restrict__ aggout)
{
    const int n = blockIdx.x;
    const int t = threadIdx.x;       // 256 = TT

    __shared__ float sx[TT + 32];
    __shared__ float sy[(TT + 20) * 9];
    __shared__ float sw0[33 * CTC];
    __shared__ float sw1[21 * CTC];
    __shared__ float sw2[CTC * CPC];
    __shared__ float bn0s[CTC], bn0t[CTC], bn2s[CPC], bn2t[CPC];

    sx[16 + t] = x[(size_t)n * TT + t];
    if (t < 16) { sx[t] = 0.f; sx[16 + TT + t] = 0.f; }
    for (int i = t; i < 33 * CTC; i += 256) sw0[i] = w0[i];
    for (int i = t; i < 21 * CTC; i += 256) sw1[i] = w1[i];
    for (int i = t; i < CTC * CPC; i += 256) sw2[i] = w2[i];
    if (t < CTC) { float s = g0[t] * rsqrtf(v0[t] + BN_EPS); bn0s[t] = s; bn0t[t] = b0[t] - m0[t] * s; }
    if (t < CPC) { float s = g2[t] * rsqrtf(v2[t] + BN_EPS); bn2s[t] = s; bn2t[t] = b2[t] - m2[t] * s; }
    __syncthreads();

    float y0[CTC];
    #pragma unroll
    for (int c = 0; c < CTC; c++) y0[c] = 0.f;
    #pragma unroll
    for (int k = 0; k < 33; k++) {
        float xv = sx[t + k];
        #pragma unroll
        for (int c = 0; c < CTC; c++) y0[c] = fmaf(xv, sw0[k * CTC + c], y0[c]);
    }
    #pragma unroll
    for (int c = 0; c < CTC; c++) y0[c] = fmaf(y0[c], bn0s[c], bn0t[c]);

    #pragma unroll
    for (int c = 0; c < CTC; c++) sy[(t + 10) * 9 + c] = y0[c];
    if (t < 10) {
        #pragma unroll
        for (int c = 0; c < CTC; c++) { sy[t * 9 + c] = 0.f; sy[(TT + 10 + t) * 9 + c] = 0.f; }
    }
    __syncthreads();

    float yc[CTC];
    #pragma unroll
    for (int c = 0; c < CTC; c++) yc[c] = 0.f;
    #pragma unroll
    for (int k = 0; k < 21; k++) {
        #pragma unroll
        for (int c = 0; c < CTC; c++) yc[c] = fmaf(sy[(t + k) * 9 + c], sw1[k * CTC + c], yc[c]);
    }
    #pragma unroll
    for (int c = 0; c < CTC; c++) yc[c] = fmaxf(yc[c], 0.f);

    float yp[CPC];
    #pragma unroll
    for (int p = 0; p < CPC; p++) yp[p] = 0.f;
    #pragma unroll
    for (int c = 0; c < CTC; c++) {
        float a = yc[c];
        #pragma unroll
        for (int p = 0; p < CPC; p++) yp[p] = fmaf(a, sw2[c * CPC + p], yp[p]);
    }
    #pragma unroll
    for (int p = 0; p < CPC; p++) yp[p] = fmaxf(fmaf(yp[p], bn2s[p], bn2t[p]), 0.f);

    #pragma unroll
    for (int p = 0; p < CPC; p++) {
        float v = yp[p];
        v += __shfl_xor_sync(0xffffffffu, v, 1);
        v += __shfl_xor_sync(0xffffffffu, v, 2);
        v += __shfl_xor_sync(0xffffffffu, v, 4);
        yp[p] = f2tf32(v * 0.125f);
    }
    if ((t & 7) == 0) {
        int tp = t >> 3;
        const size_t off = (size_t)n * FIN + tp * CPC;
        #pragma unroll
        for (int p = 0; p < CPC; p++) { h0out[off + p] = yp[p]; aggout[off + p] = yp[p]; }
    }
}

// ---------------- edge scatter-add: agg[dst] += h[src] ----------------
__global__ void scatter_kernel(const float* __restrict__ h, const int* __restrict__ ei,
                               float* __restrict__ agg, int F)
{
    const int e = blockIdx.x;
    const int f = threadIdx.x * 4;
    const int s = ei[e];
    const int d = ei[EE + e];
    const float4 v = *(const float4*)(h + (size_t)s * F + f);
    float* p = agg + (size_t)d * F + f;
    asm volatile("red.global.add.v4.f32 [%0], {%1, %2, %3, %4};"
                 :: "l"(p), "f"(v.x), "f"(v.y), "f"(v.z), "f"(v.w) : "memory");
}

// ---------------- tf32 mma.sync GEMM: C = relu(A @ Bt^T + bias) ----------------
// A: MxK row-major (tf32-valued fp32; HW truncation covers residual bits).
// Bt: NxK row-major pre-rounded tf32. 128x128 tile, BK=32, 8 warps (2x4),
// warp tile 64x32, full cp.async double-buffer, 2 CTAs/SM.
#define BM 128
#define BN 128
#define BK 32
#define LSTR 36
#define TILE_F (BM * LSTR)
#define GEMM_SMEM (4 * TILE_F * 4)          // 2 bufs x (A + B) = 73728 B

template <bool ROUND, bool DUP>
__global__ __launch_bounds__(256, 2)
void gemm_mma(const float* __restrict__ A, const float* __restrict__ Bt,
              const float* __restrict__ bias, float* __restrict__ C,
              float* __restrict__ Cdup, int M, int K, int N)
{
    extern __shared__ float sm[];
    float* Abuf[2] = { sm,          sm + 2 * TILE_F };
    float* Bbuf[2] = { sm + TILE_F, sm + 3 * TILE_F };

    const int tid  = threadIdx.x;
    const int wid  = tid >> 5;
    const int lane = tid & 31;
    const int g    = lane >> 2;
    const int tq   = lane & 3;
    const int wm   = wid >> 2;
    const int wn   = wid & 3;
    const int row0 = blockIdx.y * BM;
    const int col0 = blockIdx.x * BN;

    int lrow[4], lkq[4];
    #pragma unroll
    for (int it = 0; it < 4; it++) {
        const int l = tid + it * 256;
        lrow[it] = l >> 3;
        lkq[it]  = (l & 7) << 2;
    }

    float acc[4][4][4];
    #pragma unroll
    for (int i = 0; i < 4; i++)
        #pragma unroll
        for (int j = 0; j < 4; j++)
            #pragma unroll
            for (int r = 0; r < 4; r++) acc[i][j][r] = 0.f;

    const int nchunk = K / BK;

    auto issue = [&](int c, int buf) {
        const int k0 = c * BK;
        #pragma unroll
        for (int it = 0; it < 4; it++) {
            const uint32_t da = smem_u32(Abuf[buf] + lrow[it] * LSTR + lkq[it]);
            const float* sa = A + (size_t)(row0 + lrow[it]) * K + k0 + lkq[it];
            const int n_a = (row0 + lrow[it] < M) ? 16 : 0;
            asm volatile("cp.async.ca.shared.global [%0], [%1], 16, %2;"
                         :: "r"(da), "l"(sa), "r"(n_a));
            const uint32_t db = smem_u32(Bbuf[buf] + lrow[it] * LSTR + lkq[it]);
            const float* sb = Bt + (size_t)(col0 + lrow[it]) * K + k0 + lkq[it];
            asm volatile("cp.async.ca.shared.global [%0], [%1], 16;" :: "r"(db), "l"(sb));
        }
        asm volatile("cp.async.commit_group;");
    };

    issue(0, 0);
    if (nchunk > 1) issue(1, 1);

    for (int c = 0; c < nchunk; c++) {
        const int buf = c & 1;
        if (c + 1 < nchunk) asm volatile("cp.async.wait_group 1;");
        else                asm volatile("cp.async.wait_group 0;");
        __syncthreads();

        const float* As = Abuf[buf];
        const float* Bs = Bbuf[buf];
        #pragma unroll
        for (int kk = 0; kk < 4; kk++) {
            const int ka = kk * 8 + tq;
            uint32_t a[4][4], b[4][2];
            #pragma unroll
            for (int fm = 0; fm < 4; fm++) {
                const int r = wm * 64 + fm * 16 + g;
                a[fm][0] = __float_as_uint(As[r * LSTR + ka]);
                a[fm][1] = __float_as_uint(As[(r + 8) * LSTR + ka]);
                a[fm][2] = __float_as_uint(As[r * LSTR + ka + 4]);
                a[fm][3] = __float_as_uint(As[(r + 8) * LSTR + ka + 4]);
            }
            #pragma unroll
            for (int fn = 0; fn < 4; fn++) {
                const int nn = wn * 32 + fn * 8 + g;
                b[fn][0] = __float_as_uint(Bs[nn * LSTR + ka]);
                b[fn][1] = __float_as_uint(Bs[nn * LSTR + ka + 4]);
            }
            #pragma unroll
            for (int fm = 0; fm < 4; fm++)
                #pragma unroll
                for (int fn = 0; fn < 4; fn++)
                    mma_tf32(acc[fm][fn], a[fm], b[fn]);
        }
        __syncthreads();
        if (c + 2 < nchunk) issue(c + 2, buf);
    }

    // epilogue: bias + relu (+ optional tf32 rounding, + optional dup store)
    const int t2 = tq * 2;
    #pragma unroll
    for (int fm = 0; fm < 4; fm++) {
        const int r0 = row0 + wm * 64 + fm * 16 + g;
        #pragma unroll
        for (int fn = 0; fn < 4; fn++) {
            const int cc = col0 + wn * 32 + fn * 8 + t2;
            const float2 bv = *(const float2*)(bias + cc);
            #pragma unroll
            for (int half = 0; half < 2; half++) {
                const int rr = r0 + half * 8;
                if (rr < M) {
                    float2 o;
                    o.x = fmaxf(acc[fm][fn][half * 2 + 0] + bv.x, 0.f);
                    o.y = fmaxf(acc[fm][fn][half * 2 + 1] + bv.y, 0.f);
                    if (ROUND) { o.x = f2tf32(o.x); o.y = f2tf32(o.y); }
                    *(float2*)(C + (size_t)rr * N + cc) = o;
                    if (DUP) *(float2*)(Cdup + (size_t)rr * N + cc) = o;
                }
            }
        }
    }
}

// ---------------- per-graph mean pool (batch is sorted) ----------------
__device__ __forceinline__ int dev_lower_bound(const int* a, int n, int v) {
    int lo = 0, hi = n;
    while (lo < hi) { int m = (lo + hi) >> 1; if (a[m] < v) lo = m + 1; else hi = m; }
    return lo;
}

__global__ void pool_kernel(const float* __restrict__ h, const int* __restrict__ batch,
                            float* __restrict__ pooled)
{
    const int g = blockIdx.x;
    const int t = threadIdx.x;  // 256
    const int lo = dev_lower_bound(batch, NN, g);
    const int hi = dev_lower_bound(batch, NN, g + 1);
    float a0 = 0.f, a1 = 0.f, a2 = 0.f;
    for (int r = lo; r < hi; r++) {
        const float* row = h + (size_t)r * EMB;
        a0 += row[t]; a1 += row[t + 256]; a2 += row[t + 512];
    }
    const float inv = 1.0f / fmaxf((float)(hi - lo), 1.0f);
    pooled[g * EMB + t]       = a0 * inv;
    pooled[g * EMB + t + 256] = a1 * inv;
    pooled[g * EMB + t + 512] = a2 * inv;
}

// ---------------- head ----------------
__global__ void head_kernel(const float* __restrict__ pooled, const float* __restrict__ dw,
                            const float* __restrict__ db, float* __restrict__ out)
{
    const int g = blockIdx.x;
    const int t = threadIdx.x;  // 128
    float p0 = 0.f, p1 = 0.f, p2 = 0.f, p3 = 0.f;
    for (int k = t; k < EMB; k += 128) {
        const float pv = pooled[g * EMB + k];
        const float4 w = *(const float4*)(dw + k * 4);
        p0 = fmaf(pv, w.x, p0); p1 = fmaf(pv, w.y, p1);
        p2 = fmaf(pv, w.z, p2); p3 = fmaf(pv, w.w, p3);
    }
    __shared__ float s[4][128];
    s[0][t] = p0; s[1][t] = p1; s[2][t] = p2; s[3][t] = p3;
    __syncthreads();
    if (t < 4) {
        float sum = 0.f;
        for (int i = 0; i < 128; i++) sum += s[t][i];
        s[t][0] = sum + db[t];
    }
    __syncthreads();
    if (t == 0) {
        float l0 = s[0][0], l1 = s[1][0], l2 = s[2][0], l3 = s[3][0];
        float m = fmaxf(fmaxf(l0, l1), fmaxf(l2, l3));
        float lse = logf(expf(l0 - m) + expf(l1 - m) + expf(l2 - m) + expf(l3 - m)) + m;
        float* o = out + g * 4;
        o[0] = l0 - lse; o[1] = l1 - lse; o[2] = l2 - lse; o[3] = l3 - lse;
    }
}

// ---------------- launch ----------------
extern "C" void kernel_launch(void* const* d_in, const int* in_sizes, int n_in,
                              void* d_out, int out_size)
{
    const float* x        = (const float*)d_in[0];
    const int*   ei       = (const int*)d_in[1];
    const int*   batch    = (const int*)d_in[2];
    const float* conv0_w  = (const float*)d_in[3];
    const float* bn0_g    = (const float*)d_in[4];
    const float* bn0_b    = (const float*)d_in[5];
    const float* bn0_m    = (const float*)d_in[6];
    const float* bn0_v    = (const float*)d_in[7];
    const float* conv1_w  = (const float*)d_in[8];
    const float* conv2_w  = (const float*)d_in[9];
    const float* bn2_g    = (const float*)d_in[10];
    const float* bn2_b    = (const float*)d_in[11];
    const float* bn2_m    = (const float*)d_in[12];
    const float* bn2_v    = (const float*)d_in[13];
    const float* g1w1     = (const float*)d_in[14];
    const float* g1b1     = (const float*)d_in[15];
    const float* g1w2     = (const float*)d_in[16];
    const float* g1b2     = (const float*)d_in[17];
    const float* g2w1     = (const float*)d_in[18];
    const float* g2b1     = (const float*)d_in[19];
    const float* g2w2     = (const float*)d_in[20];
    const float* g2b2     = (const float*)d_in[21];
    const float* dense_w  = (const float*)d_in[22];
    const float* dense_b  = (const float*)d_in[23];
    float* out = (float*)d_out;

    float *h0, *agg, *z, *h1, *pooled, *wt1, *wt2, *wt3, *wt4;
    cudaGetSymbolAddress((void**)&h0,     g_h0);
    cudaGetSymbolAddress((void**)&agg,    g_agg);
    cudaGetSymbolAddress((void**)&z,      g_z);
    cudaGetSymbolAddress((void**)&h1,     g_h1);
    cudaGetSymbolAddress((void**)&pooled, g_pooled);
    cudaGetSymbolAddress((void**)&wt1,    g_wt1);
    cudaGetSymbolAddress((void**)&wt2,    g_wt2);
    cudaGetSymbolAddress((void**)&wt3,    g_wt3);
    cudaGetSymbolAddress((void**)&wt4,    g_wt4);

    cudaFuncSetAttribute(gemm_mma<true , false>, cudaFuncAttributeMaxDynamicSharedMemorySize, GEMM_SMEM);
    cudaFuncSetAttribute(gemm_mma<true , true >, cudaFuncAttributeMaxDynamicSharedMemorySize, GEMM_SMEM);
    cudaFuncSetAttribute(gemm_mma<false, false>, cudaFuncAttributeMaxDynamicSharedMemorySize, GEMM_SMEM);

    const dim3 ggrid(EMB / 128, (NN + 127) / 128);

    // all 4 weight transposes in one launch
    transpose_all_kernel<<<dim3(EMB / 32, EMB / 32, 4), dim3(32, 8)>>>(
        g1w1, g1w2, g2w1, g2w2, wt1, wt2, wt3, wt4);

    // temporal conv stack -> h0 and agg (=h0)
    conv_kernel<<<NN, 256>>>(x, conv0_w, bn0_g, bn0_b, bn0_m, bn0_v,
                             conv1_w, conv2_w, bn2_g, bn2_b, bn2_m, bn2_v, h0, agg);
    // GIN1: agg = h0 + sum(neigh)
    scatter_kernel<<<EE, FIN / 4>>>(h0, ei, agg, FIN);
    gemm_mma<true , false><<<ggrid, 256, GEMM_SMEM>>>(agg, wt1, g1b1, z, nullptr, NN, FIN, EMB);
    gemm_mma<true , true ><<<ggrid, 256, GEMM_SMEM>>>(z,   wt2, g1b2, h1, agg,    NN, EMB, EMB);
    // GIN2: agg = h1 + sum(neigh)
    scatter_kernel<<<EE, EMB / 4>>>(h1, ei, agg, EMB);
    gemm_mma<true , false><<<ggrid, 256, GEMM_SMEM>>>(agg, wt3, g2b1, z,  nullptr, NN, EMB, EMB);
    gemm_mma<false, false><<<ggrid, 256, GEMM_SMEM>>>(z,   wt4, g2b2, h1, nullptr, NN, EMB, EMB);
    // pool + head
    pool_kernel<<<GG, 256>>>(h1, batch, pooled);
    head_kernel<<<GG, 128>>>(pooled, dense_w, dense_b, out);
}

// round 5
// speedup vs baseline: 2.5644x; 1.2298x over previous
#include <cuda_runtime.h>
#include <math.h>
#include <stdint.h>

#define NN   20000
#define TT   256
#define EE   320000
#define GG   64
#define CTC  8
#define CPC  16
#define EMB  768
#define FIN  512
#define BN_EPS 1e-5f

// ---------------- scratch (no allocations allowed) ----------------
__device__ float g_h0[(size_t)NN * FIN];     // conv output, N x 512
__device__ float g_agg[(size_t)NN * EMB];    // X = h + sum(neigh)
__device__ float g_z[(size_t)NN * EMB];      // gin hidden
__device__ float g_h1[(size_t)NN * EMB];     // gin1 output, then h2
__device__ float g_pooled[GG * EMB];
__device__ float g_wt1[EMB * FIN];
__device__ float g_wt2[EMB * EMB];
__device__ float g_wt3[EMB * EMB];
__device__ float g_wt4[EMB * EMB];
__device__ int   g_deg[NN];                  // histogram, then cursor
__device__ int   g_off[NN + 1];
__device__ int   g_srcs[EE];

// ---------------- helpers ----------------
__device__ __forceinline__ uint32_t smem_u32(const void* p) {
    uint32_t a;
    asm("{ .reg .u64 t; cvta.to.shared.u64 t, %1; cvt.u32.u64 %0, t; }" : "=r"(a) : "l"(p));
    return a;
}
__device__ __forceinline__ float f2tf32(float v) {
    uint32_t o;
    asm("cvt.rna.tf32.f32 %0, %1;" : "=r"(o) : "f"(v));
    return __uint_as_float(o);
}
__device__ __forceinline__ void mma_tf32(float* c, const uint32_t* a, const uint32_t* b) {
    asm volatile("mma.sync.aligned.m16n8k8.row.col.f32.tf32.tf32.f32 "
        "{%0,%1,%2,%3}, {%4,%5,%6,%7}, {%8,%9}, {%0,%1,%2,%3};"
        : "+f"(c[0]), "+f"(c[1]), "+f"(c[2]), "+f"(c[3])
        : "r"(a[0]), "r"(a[1]), "r"(a[2]), "r"(a[3]), "r"(b[0]), "r"(b[1]));
}

// ---------------- weight transposes, all four in one launch ----------------
__global__ void transpose_all_kernel(const float* __restrict__ w1, const float* __restrict__ w2,
                                     const float* __restrict__ w3, const float* __restrict__ w4,
                                     float* __restrict__ t1, float* __restrict__ t2,
                                     float* __restrict__ t3, float* __restrict__ t4)
{
    const int which = blockIdx.z;
    const float* W; float* Wt; int K;
    if (which == 0)      { W = w1; Wt = t1; K = FIN; }
    else if (which == 1) { W = w2; Wt = t2; K = EMB; }
    else if (which == 2) { W = w3; Wt = t3; K = EMB; }
    else                 { W = w4; Wt = t4; K = EMB; }
    const int kb = blockIdx.x * 32, nb = blockIdx.y * 32;
    if (kb >= K) return;
    __shared__ float tile[32][33];
    const int tx = threadIdx.x, ty = threadIdx.y;  // 32 x 8
    #pragma unroll
    for (int i = ty; i < 32; i += 8)
        tile[i][tx] = W[(size_t)(kb + i) * EMB + nb + tx];
    __syncthreads();
    #pragma unroll
    for (int i = ty; i < 32; i += 8)
        Wt[(size_t)(nb + i) * K + kb + tx] = f2tf32(tile[tx][i]);
}

// ---------------- edge sort: histogram -> scan -> fill ----------------
__global__ void zero_deg_kernel(int* __restrict__ deg) {
    int i = blockIdx.x * 256 + threadIdx.x;
    if (i < NN) deg[i] = 0;
}
__global__ void hist_kernel(const int* __restrict__ ei, int* __restrict__ deg) {
    int e = blockIdx.x * 256 + threadIdx.x;
    if (e < EE) atomicAdd(&deg[ei[EE + e]], 1);
}
// single-block exclusive scan of deg[0..NN) -> off; zeroes deg (reused as cursor)
__global__ __launch_bounds__(1024)
void scan_kernel(int* __restrict__ deg, int* __restrict__ off) {
    __shared__ int wsum[32];
    __shared__ int sc;
    const int tid = threadIdx.x;
    const int lane = tid & 31, w = tid >> 5;
    if (tid == 0) sc = 0;
    __syncthreads();
    for (int base = 0; base < NN; base += 1024) {
        const int i = base + tid;
        const int v = (i < NN) ? deg[i] : 0;
        int x = v;
        #pragma unroll
        for (int d = 1; d < 32; d <<= 1) { int y = __shfl_up_sync(~0u, x, d); if (lane >= d) x += y; }
        if (lane == 31) wsum[w] = x;
        __syncthreads();
        if (w == 0) {
            int t = wsum[lane];
            #pragma unroll
            for (int d = 1; d < 32; d <<= 1) { int y = __shfl_up_sync(~0u, t, d); if (lane >= d) t += y; }
            wsum[lane] = t;
        }
        __syncthreads();
        const int warpoff = (w == 0) ? 0 : wsum[w - 1];
        const int excl = x - v + warpoff;
        if (i < NN) { off[i] = sc + excl; deg[i] = 0; }
        const int total = wsum[31];
        __syncthreads();
        if (tid == 0) sc += total;
        __syncthreads();
    }
    if (tid == 0) off[NN] = EE;
}
__global__ void fill_kernel(const int* __restrict__ ei, const int* __restrict__ off,
                            int* __restrict__ cursor, int* __restrict__ srcs) {
    int e = blockIdx.x * 256 + threadIdx.x;
    if (e >= EE) return;
    const int d = ei[EE + e];
    const int p = off[d] + atomicAdd(&cursor[d], 1);
    srcs[p] = ei[e];
}

// ---------------- gather: agg[n] = h[n] + sum_{e: dst=n} h[src[e]] ----------------
template <int F>
__global__ void gather_kernel(const float* __restrict__ h, const int* __restrict__ off,
                              const int* __restrict__ srcs, float* __restrict__ agg)
{
    const int n = blockIdx.x;
    const int f = threadIdx.x * 4;   // blockDim = F/4
    const int lo = off[n], hi = off[n + 1];
    float4 acc = *(const float4*)(h + (size_t)n * F + f);
    int r = lo;
    for (; r + 4 <= hi; r += 4) {
        const int s0 = srcs[r], s1 = srcs[r + 1], s2 = srcs[r + 2], s3 = srcs[r + 3];
        const float4 v0 = *(const float4*)(h + (size_t)s0 * F + f);
        const float4 v1 = *(const float4*)(h + (size_t)s1 * F + f);
        const float4 v2 = *(const float4*)(h + (size_t)s2 * F + f);
        const float4 v3 = *(const float4*)(h + (size_t)s3 * F + f);
        acc.x += v0.x + v1.x + v2.x + v3.x;
        acc.y += v0.y + v1.y + v2.y + v3.y;
        acc.z += v0.z + v1.z + v2.z + v3.z;
        acc.w += v0.w + v1.w + v2.w + v3.w;
    }
    for (; r < hi; r++) {
        const int s = srcs[r];
        const float4 v = *(const float4*)(h + (size_t)s * F + f);
        acc.x += v.x; acc.y += v.y; acc.z += v.z; acc.w += v.w;
    }
    acc.x = f2tf32(acc.x); acc.y = f2tf32(acc.y);
    acc.z = f2tf32(acc.z); acc.w = f2tf32(acc.w);
    *(float4*)(agg + (size_t)n * F + f) = acc;
}

// ---------------- temporal conv stack: per-node block ----------------
__global__ __launch_bounds__(256)
void conv_kernel(const float* __restrict__ x,
                 const float* __restrict__ w0,
                 const float* __restrict__ g0, const float* __restrict__ b0,
                 const float* __restrict__ m0, const float* __restrict__ v0,
                 const float* __restrict__ w1,
                 const float* __restrict__ w2,
                 const float* __restrict__ g2, const float* __restrict__ b2,
                 const float* __restrict__ m2, const float* __restrict__ v2,
                 float* __restrict__ h0out)
{
    const int n = blockIdx.x;
    const int t = threadIdx.x;       // 256 = TT

    __shared__ float sx[TT + 32];
    __shared__ float sy[(TT + 20) * 9];
    __shared__ float sw0[33 * CTC];
    __shared__ float sw1[21 * CTC];
    __shared__ float sw2[CTC * CPC];
    __shared__ float bn0s[CTC], bn0t[CTC], bn2s[CPC], bn2t[CPC];

    sx[16 + t] = x[(size_t)n * TT + t];
    if (t < 16) { sx[t] = 0.f; sx[16 + TT + t] = 0.f; }
    for (int i = t; i < 33 * CTC; i += 256) sw0[i] = w0[i];
    for (int i = t; i < 21 * CTC; i += 256) sw1[i] = w1[i];
    for (int i = t; i < CTC * CPC; i += 256) sw2[i] = w2[i];
    if (t < CTC) { float s = g0[t] * rsqrtf(v0[t] + BN_EPS); bn0s[t] = s; bn0t[t] = b0[t] - m0[t] * s; }
    if (t < CPC) { float s = g2[t] * rsqrtf(v2[t] + BN_EPS); bn2s[t] = s; bn2t[t] = b2[t] - m2[t] * s; }
    __syncthreads();

    float y0[CTC];
    #pragma unroll
    for (int c = 0; c < CTC; c++) y0[c] = 0.f;
    #pragma unroll
    for (int k = 0; k < 33; k++) {
        float xv = sx[t + k];
        #pragma unroll
        for (int c = 0; c < CTC; c++) y0[c] = fmaf(xv, sw0[k * CTC + c], y0[c]);
    }
    #pragma unroll
    for (int c = 0; c < CTC; c++) y0[c] = fmaf(y0[c], bn0s[c], bn0t[c]);

    #pragma unroll
    for (int c = 0; c < CTC; c++) sy[(t + 10) * 9 + c] = y0[c];
    if (t < 10) {
        #pragma unroll
        for (int c = 0; c < CTC; c++) { sy[t * 9 + c] = 0.f; sy[(TT + 10 + t) * 9 + c] = 0.f; }
    }
    __syncthreads();

    float yc[CTC];
    #pragma unroll
    for (int c = 0; c < CTC; c++) yc[c] = 0.f;
    #pragma unroll
    for (int k = 0; k < 21; k++) {
        #pragma unroll
        for (int c = 0; c < CTC; c++) yc[c] = fmaf(sy[(t + k) * 9 + c], sw1[k * CTC + c], yc[c]);
    }
    #pragma unroll
    for (int c = 0; c < CTC; c++) yc[c] = fmaxf(yc[c], 0.f);

    float yp[CPC];
    #pragma unroll
    for (int p = 0; p < CPC; p++) yp[p] = 0.f;
    #pragma unroll
    for (int c = 0; c < CTC; c++) {
        float a = yc[c];
        #pragma unroll
        for (int p = 0; p < CPC; p++) yp[p] = fmaf(a, sw2[c * CPC + p], yp[p]);
    }
    #pragma unroll
    for (int p = 0; p < CPC; p++) yp[p] = fmaxf(fmaf(yp[p], bn2s[p], bn2t[p]), 0.f);

    #pragma unroll
    for (int p = 0; p < CPC; p++) {
        float v = yp[p];
        v += __shfl_xor_sync(0xffffffffu, v, 1);
        v += __shfl_xor_sync(0xffffffffu, v, 2);
        v += __shfl_xor_sync(0xffffffffu, v, 4);
        yp[p] = f2tf32(v * 0.125f);
    }
    if ((t & 7) == 0) {
        int tp = t >> 3;
        const size_t off = (size_t)n * FIN + tp * CPC;
        #pragma unroll
        for (int p = 0; p < CPC; p++) h0out[off + p] = yp[p];
    }
}

// ---------------- tf32 mma.sync GEMM: C = relu(A @ Bt^T + bias) ----------------
#define BM 128
#define BN 128
#define BK 32
#define LSTR 36
#define TILE_F (BM * LSTR)
#define GEMM_SMEM (4 * TILE_F * 4)          // 2 bufs x (A + B) = 73728 B

#define LOADF(a, b, ka_) do { \
    _Pragma("unroll") \
    for (int fm = 0; fm < 4; fm++) { \
        const int r_ = wm * 64 + fm * 16 + g; \
        a[fm][0] = __float_as_uint(As[r_ * LSTR + (ka_)]); \
        a[fm][1] = __float_as_uint(As[(r_ + 8) * LSTR + (ka_)]); \
        a[fm][2] = __float_as_uint(As[r_ * LSTR + (ka_) + 4]); \
        a[fm][3] = __float_as_uint(As[(r_ + 8) * LSTR + (ka_) + 4]); \
    } \
    _Pragma("unroll") \
    for (int fn = 0; fn < 4; fn++) { \
        const int nn_ = wn * 32 + fn * 8 + g; \
        b[fn][0] = __float_as_uint(Bs[nn_ * LSTR + (ka_)]); \
        b[fn][1] = __float_as_uint(Bs[nn_ * LSTR + (ka_) + 4]); \
    } \
} while (0)

#define MMAS(a, b) do { \
    _Pragma("unroll") \
    for (int fm = 0; fm < 4; fm++) \
        _Pragma("unroll") \
        for (int fn = 0; fn < 4; fn++) \
            mma_tf32(acc[fm][fn], a[fm], b[fn]); \
} while (0)

template <bool ROUND>
__global__ __launch_bounds__(256, 2)
void gemm_mma(const float* __restrict__ A, const float* __restrict__ Bt,
              const float* __restrict__ bias, float* __restrict__ C,
              int M, int K, int N)
{
    extern __shared__ float sm[];
    float* Abuf[2] = { sm,          sm + 2 * TILE_F };
    float* Bbuf[2] = { sm + TILE_F, sm + 3 * TILE_F };

    const int tid  = threadIdx.x;
    const int wid  = tid >> 5;
    const int lane = tid & 31;
    const int g    = lane >> 2;
    const int tq   = lane & 3;
    const int wm   = wid >> 2;
    const int wn   = wid & 3;
    const int row0 = blockIdx.y * BM;
    const int col0 = blockIdx.x * BN;

    int lrow[4], lkq[4];
    #pragma unroll
    for (int it = 0; it < 4; it++) {
        const int l = tid + it * 256;
        lrow[it] = l >> 3;
        lkq[it]  = (l & 7) << 2;
    }

    float acc[4][4][4];
    #pragma unroll
    for (int i = 0; i < 4; i++)
        #pragma unroll
        for (int j = 0; j < 4; j++)
            #pragma unroll
            for (int r = 0; r < 4; r++) acc[i][j][r] = 0.f;

    const int nchunk = K / BK;

    auto issue = [&](int c, int buf) {
        const int k0 = c * BK;
        #pragma unroll
        for (int it = 0; it < 4; it++) {
            const uint32_t da = smem_u32(Abuf[buf] + lrow[it] * LSTR + lkq[it]);
            const float* sa = A + (size_t)(row0 + lrow[it]) * K + k0 + lkq[it];
            const int n_a = (row0 + lrow[it] < M) ? 16 : 0;
            asm volatile("cp.async.ca.shared.global [%0], [%1], 16, %2;"
                         :: "r"(da), "l"(sa), "r"(n_a));
            const uint32_t db = smem_u32(Bbuf[buf] + lrow[it] * LSTR + lkq[it]);
            const float* sb = Bt + (size_t)(col0 + lrow[it]) * K + k0 + lkq[it];
            asm volatile("cp.async.ca.shared.global [%0], [%1], 16;" :: "r"(db), "l"(sb));
        }
        asm volatile("cp.async.commit_group;");
    };

    issue(0, 0);
    if (nchunk > 1) issue(1, 1);

    for (int c = 0; c < nchunk; c++) {
        const int buf = c & 1;
        if (c + 1 < nchunk) asm volatile("cp.async.wait_group 1;");
        else                asm volatile("cp.async.wait_group 0;");
        __syncthreads();

        const float* As = Abuf[buf];
        const float* Bs = Bbuf[buf];
        uint32_t af0[4][4], bf0[4][2], af1[4][4], bf1[4][2];
        LOADF(af0, bf0, tq);
        LOADF(af1, bf1, 8 + tq);
        MMAS(af0, bf0);
        LOADF(af0, bf0, 16 + tq);
        MMAS(af1, bf1);
        LOADF(af1, bf1, 24 + tq);
        MMAS(af0, bf0);
        MMAS(af1, bf1);
        __syncthreads();
        if (c + 2 < nchunk) issue(c + 2, buf);
    }

    // epilogue: bias + relu (+ optional tf32 rounding)
    const int t2 = tq * 2;
    #pragma unroll
    for (int fm = 0; fm < 4; fm++) {
        const int r0 = row0 + wm * 64 + fm * 16 + g;
        #pragma unroll
        for (int fn = 0; fn < 4; fn++) {
            const int cc = col0 + wn * 32 + fn * 8 + t2;
            const float2 bv = *(const float2*)(bias + cc);
            #pragma unroll
            for (int half = 0; half < 2; half++) {
                const int rr = r0 + half * 8;
                if (rr < M) {
                    float2 o;
                    o.x = fmaxf(acc[fm][fn][half * 2 + 0] + bv.x, 0.f);
                    o.y = fmaxf(acc[fm][fn][half * 2 + 1] + bv.y, 0.f);
                    if (ROUND) { o.x = f2tf32(o.x); o.y = f2tf32(o.y); }
                    *(float2*)(C + (size_t)rr * N + cc) = o;
                }
            }
        }
    }
}

// ---------------- per-graph mean pool (batch is sorted) ----------------
__device__ __forceinline__ int dev_lower_bound(const int* a, int n, int v) {
    int lo = 0, hi = n;
    while (lo < hi) { int m = (lo + hi) >> 1; if (a[m] < v) lo = m + 1; else hi = m; }
    return lo;
}

__global__ void pool_kernel(const float* __restrict__ h, const int* __restrict__ batch,
                            float* __restrict__ pooled)
{
    const int g = blockIdx.x;
    const int t = threadIdx.x;  // 256
    const int lo = dev_lower_bound(batch, NN, g);
    const int hi = dev_lower_bound(batch, NN, g + 1);
    float a0 = 0.f, a1 = 0.f, a2 = 0.f;
    for (int r = lo; r < hi; r++) {
        const float* row = h + (size_t)r * EMB;
        a0 += row[t]; a1 += row[t + 256]; a2 += row[t + 512];
    }
    const float inv = 1.0f / fmaxf((float)(hi - lo), 1.0f);
    pooled[g * EMB + t]       = a0 * inv;
    pooled[g * EMB + t + 256] = a1 * inv;
    pooled[g * EMB + t + 512] = a2 * inv;
}

// ---------------- head ----------------
__global__ void head_kernel(const float* __restrict__ pooled, const float* __restrict__ dw,
                            const float* __restrict__ db, float* __restrict__ out)
{
    const int g = blockIdx.x;
    const int t = threadIdx.x;  // 128
    float p0 = 0.f, p1 = 0.f, p2 = 0.f, p3 = 0.f;
    for (int k = t; k < EMB; k += 128) {
        const float pv = pooled[g * EMB + k];
        const float4 w = *(const float4*)(dw + k * 4);
        p0 = fmaf(pv, w.x, p0); p1 = fmaf(pv, w.y, p1);
        p2 = fmaf(pv, w.z, p2); p3 = fmaf(pv, w.w, p3);
    }
    __shared__ float s[4][128];
    s[0][t] = p0; s[1][t] = p1; s[2][t] = p2; s[3][t] = p3;
    __syncthreads();
    if (t < 4) {
        float sum = 0.f;
        for (int i = 0; i < 128; i++) sum += s[t][i];
        s[t][0] = sum + db[t];
    }
    __syncthreads();
    if (t == 0) {
        float l0 = s[0][0], l1 = s[1][0], l2 = s[2][0], l3 = s[3][0];
        float m = fmaxf(fmaxf(l0, l1), fmaxf(l2, l3));
        float lse = logf(expf(l0 - m) + expf(l1 - m) + expf(l2 - m) + expf(l3 - m)) + m;
        float* o = out + g * 4;
        o[0] = l0 - lse; o[1] = l1 - lse; o[2] = l2 - lse; o[3] = l3 - lse;
    }
}

// ---------------- launch ----------------
extern "C" void kernel_launch(void* const* d_in, const int* in_sizes, int n_in,
                              void* d_out, int out_size)
{
    const float* x        = (const float*)d_in[0];
    const int*   ei       = (const int*)d_in[1];
    const int*   batch    = (const int*)d_in[2];
    const float* conv0_w  = (const float*)d_in[3];
    const float* bn0_g    = (const float*)d_in[4];
    const float* bn0_b    = (const float*)d_in[5];
    const float* bn0_m    = (const float*)d_in[6];
    const float* bn0_v    = (const float*)d_in[7];
    const float* conv1_w  = (const float*)d_in[8];
    const float* conv2_w  = (const float*)d_in[9];
    const float* bn2_g    = (const float*)d_in[10];
    const float* bn2_b    = (const float*)d_in[11];
    const float* bn2_m    = (const float*)d_in[12];
    const float* bn2_v    = (const float*)d_in[13];
    const float* g1w1     = (const float*)d_in[14];
    const float* g1b1     = (const float*)d_in[15];
    const float* g1w2     = (const float*)d_in[16];
    const float* g1b2     = (const float*)d_in[17];
    const float* g2w1     = (const float*)d_in[18];
    const float* g2b1     = (const float*)d_in[19];
    const float* g2w2     = (const float*)d_in[20];
    const float* g2b2     = (const float*)d_in[21];
    const float* dense_w  = (const float*)d_in[22];
    const float* dense_b  = (const float*)d_in[23];
    float* out = (float*)d_out;

    float *h0, *agg, *z, *h1, *pooled, *wt1, *wt2, *wt3, *wt4;
    int *deg, *off, *srcs;
    cudaGetSymbolAddress((void**)&h0,     g_h0);
    cudaGetSymbolAddress((void**)&agg,    g_agg);
    cudaGetSymbolAddress((void**)&z,      g_z);
    cudaGetSymbolAddress((void**)&h1,     g_h1);
    cudaGetSymbolAddress((void**)&pooled, g_pooled);
    cudaGetSymbolAddress((void**)&wt1,    g_wt1);
    cudaGetSymbolAddress((void**)&wt2,    g_wt2);
    cudaGetSymbolAddress((void**)&wt3,    g_wt3);
    cudaGetSymbolAddress((void**)&wt4,    g_wt4);
    cudaGetSymbolAddress((void**)&deg,    g_deg);
    cudaGetSymbolAddress((void**)&off,    g_off);
    cudaGetSymbolAddress((void**)&srcs,   g_srcs);

    cudaFuncSetAttribute(gemm_mma<true >, cudaFuncAttributeMaxDynamicSharedMemorySize, GEMM_SMEM);
    cudaFuncSetAttribute(gemm_mma<false>, cudaFuncAttributeMaxDynamicSharedMemorySize, GEMM_SMEM);

    const dim3 ggrid(EMB / 128, (NN + 127) / 128);

    // weights + edge sort + conv (independent)
    transpose_all_kernel<<<dim3(EMB / 32, EMB / 32, 4), dim3(32, 8)>>>(
        g1w1, g1w2, g2w1, g2w2, wt1, wt2, wt3, wt4);
    zero_deg_kernel<<<(NN + 255) / 256, 256>>>(deg);
    hist_kernel<<<(EE + 255) / 256, 256>>>(ei, deg);
    scan_kernel<<<1, 1024>>>(deg, off);
    fill_kernel<<<(EE + 255) / 256, 256>>>(ei, off, deg, srcs);
    conv_kernel<<<NN, 256>>>(x, conv0_w, bn0_g, bn0_b, bn0_m, bn0_v,
                             conv1_w, conv2_w, bn2_g, bn2_b, bn2_m, bn2_v, h0);
    // GIN1
    gather_kernel<FIN><<<NN, FIN / 4>>>(h0, off, srcs, agg);
    gemm_mma<true ><<<ggrid, 256, GEMM_SMEM>>>(agg, wt1, g1b1, z,  NN, FIN, EMB);
    gemm_mma<true ><<<ggrid, 256, GEMM_SMEM>>>(z,   wt2, g1b2, h1, NN, EMB, EMB);
    // GIN2
    gather_kernel<EMB><<<NN, EMB / 4>>>(h1, off, srcs, agg);
    gemm_mma<true ><<<ggrid, 256, GEMM_SMEM>>>(agg, wt3, g2b1, z,  NN, EMB, EMB);
    gemm_mma<false><<<ggrid, 256, GEMM_SMEM>>>(z,   wt4, g2b2, h1, NN, EMB, EMB);
    // pool + head
    pool_kernel<<<GG, 256>>>(h1, batch, pooled);
    head_kernel<<<GG, 128>>>(pooled, dense_w, dense_b, out);
}